// round 1
// baseline (speedup 1.0000x reference)
#include <cuda_runtime.h>

// ---------------------------------------------------------------------------
// GATv2 (H=2, EMB=64) + fused final linear, collapsed to scalar-per-edge form.
//
// Per-edge:  logit_h = 0.6*L_h + 0.4*sum_c att_hc*|z_hc|,
//            z_hc = s*Wl + t*Wr + a*We + b,  L_h = s*P_h + t*Q_h + a*R_h + B_h
// Per-node:  S_ih = sum_e alpha_eh * x[src_e]   (softmax without max-shift)
// Output:    out[i,:] = S_i0*A0 + S_i1*A1 + C   (rank-2, 128-wide)
// ---------------------------------------------------------------------------

#define NODE_CAP 131072
#define EPT 4

__device__ float4 g_accum[NODE_CAP];    // {den0, num0, den1, num1}
__device__ float2 g_degattr[NODE_CAP];  // {deg, attr_sum}
__device__ float2 g_S[NODE_CAP];        // {S0, S1}
__device__ unsigned long long g_wlA[64], g_wrA[64], g_weA[64], g_bA[64], g_sm[64];
__device__ unsigned long long g_lin[4]; // packed {head0,head1}: P', Q', R', B'
__device__ __align__(16) float g_A0[128];
__device__ __align__(16) float g_A1[128];
__device__ __align__(16) float g_C[128];
__device__ int g_idx64;

// ---- f32x2 helpers (packed two fp32 in one 64-bit reg) ----
__device__ __forceinline__ unsigned long long pack2(float lo, float hi) {
    unsigned long long r;
    asm("mov.b64 %0, {%1, %2};" : "=l"(r) : "r"(__float_as_uint(lo)), "r"(__float_as_uint(hi)));
    return r;
}
__device__ __forceinline__ void unpack2(unsigned long long v, float& lo, float& hi) {
    unsigned a, b;
    asm("mov.b64 {%0, %1}, %2;" : "=r"(a), "=r"(b) : "l"(v));
    lo = __uint_as_float(a); hi = __uint_as_float(b);
}
__device__ __forceinline__ unsigned long long fma2(unsigned long long a, unsigned long long b, unsigned long long c) {
    unsigned long long d;
    asm("fma.rn.f32x2 %0, %1, %2, %3;" : "=l"(d) : "l"(a), "l"(b), "l"(c));
    return d;
}
__device__ __forceinline__ unsigned long long add2(unsigned long long a, unsigned long long b) {
    unsigned long long d;
    asm("add.rn.f32x2 %0, %1, %2;" : "=l"(d) : "l"(a), "l"(b));
    return d;
}
// (z & 0x7fffffff) | signmask  per 32-bit half: one LOP3 each (immLut 0xEA)
__device__ __forceinline__ unsigned long long absor2(unsigned long long z, unsigned mlo, unsigned mhi) {
    unsigned lo, hi, rlo, rhi;
    asm("mov.b64 {%0, %1}, %2;" : "=r"(lo), "=r"(hi) : "l"(z));
    asm("lop3.b32 %0, %1, 0x7fffffff, %2, 0xEA;" : "=r"(rlo) : "r"(lo), "r"(mlo));
    asm("lop3.b32 %0, %1, 0x7fffffff, %2, 0xEA;" : "=r"(rhi) : "r"(hi), "r"(mhi));
    unsigned long long r;
    asm("mov.b64 %0, {%1, %2};" : "=l"(r) : "r"(rlo), "r"(rhi));
    return r;
}
__device__ __forceinline__ float ex2f(float x) {
    float r;
    asm("ex2.approx.f32 %0, %1;" : "=f"(r) : "f"(x));
    return r;
}

// ---------------------------------------------------------------------------
__global__ void k_init(const void* __restrict__ eidx, int n,
                       const float* __restrict__ Wl, const float* __restrict__ bl,
                       const float* __restrict__ Wr, const float* __restrict__ br,
                       const float* __restrict__ We, const float* __restrict__ att)
{
    const float LOG2E = 1.4426950408889634f;
    const float kap = 0.4f * LOG2E;
    const float lam = 0.6f * LOG2E;
    int tid = threadIdx.x;
    if (tid < 64) {
        int c = tid;
        float a0 = att[c], a1 = att[64 + c];
        float b0 = bl[c] + br[c], b1 = bl[64 + c] + br[64 + c];
        g_wlA[c] = pack2(kap * a0 * Wl[c], kap * a1 * Wl[64 + c]);
        g_wrA[c] = pack2(kap * a0 * Wr[c], kap * a1 * Wr[64 + c]);
        g_weA[c] = pack2(kap * a0 * We[c], kap * a1 * We[64 + c]);
        g_bA[c]  = pack2(kap * a0 * b0,    kap * a1 * b1);
        unsigned m0 = __float_as_uint(a0) & 0x80000000u;
        unsigned m1 = __float_as_uint(a1) & 0x80000000u;
        g_sm[c] = ((unsigned long long)m1 << 32) | (unsigned long long)m0;
    }
    if (tid == 0) {
        float P0 = 0, P1 = 0, Q0 = 0, Q1 = 0, R0 = 0, R1 = 0, B0 = 0, B1 = 0;
        for (int c = 0; c < 64; c++) {
            float a0 = att[c], a1 = att[64 + c];
            P0 += a0 * Wl[c];  P1 += a1 * Wl[64 + c];
            Q0 += a0 * Wr[c];  Q1 += a1 * Wr[64 + c];
            R0 += a0 * We[c];  R1 += a1 * We[64 + c];
            B0 += a0 * (bl[c] + br[c]); B1 += a1 * (bl[64 + c] + br[64 + c]);
        }
        g_lin[0] = pack2(lam * P0, lam * P1);
        g_lin[1] = pack2(lam * Q0, lam * Q1);
        g_lin[2] = pack2(lam * R0, lam * R1);
        g_lin[3] = pack2(lam * B0, lam * B1);
        // edge_index dtype detection: int64 values are all < n; int32 data
        // reinterpreted as int64 combines two indices -> >= 2^32 almost surely.
        const unsigned long long* p = (const unsigned long long*)eidx;
        int is64 = 1;
        for (int i = 0; i < 16; i++)
            if (p[i] >= (unsigned long long)n) is64 = 0;
        g_idx64 = is64;
    }
}

__global__ void k_zero(int n)
{
    int i = blockIdx.x * blockDim.x + threadIdx.x;
    if (i < n) {
        g_accum[i] = make_float4(0.f, 0.f, 0.f, 0.f);
        g_degattr[i] = make_float2(0.f, 0.f);
    }
}

// ---------------------------------------------------------------------------
__global__ void __launch_bounds__(256) k_edges(
    const float* __restrict__ x, const void* __restrict__ eidx,
    const float* __restrict__ eattr, int n, int E)
{
    __shared__ unsigned long long s_wl[64], s_wr[64], s_we[64], s_b[64], s_m[64];
    int tid = threadIdx.x;
    if (tid < 64) {
        s_wl[tid] = g_wlA[tid]; s_wr[tid] = g_wrA[tid]; s_we[tid] = g_weA[tid];
        s_b[tid]  = g_bA[tid];  s_m[tid]  = g_sm[tid];
    }
    __syncthreads();

    int base = (blockIdx.x * blockDim.x + tid) * EPT;
    if (base >= E) return;
    int idx64 = g_idx64;
    const long long* p64 = (const long long*)eidx;
    const int* p32 = (const int*)eidx;

    float sv[EPT], av[EPT];
    unsigned long long s2[EPT], t2[EPT], a2[EPT], acc[EPT];
    int dsti[EPT];
    bool ok[EPT];

#pragma unroll
    for (int k = 0; k < EPT; k++) {
        int e = base + k;
        ok[k] = (e < E);
        int si = 0, di = 0;
        float aa = 0.f, s = 0.f, t = 0.f;
        if (ok[k]) {
            if (idx64) { si = (int)p64[e]; di = (int)p64[E + e]; }
            else       { si = p32[e];      di = p32[E + e]; }
            aa = eattr[e];
            s = x[si]; t = x[di];
        }
        dsti[k] = di; sv[k] = s; av[k] = aa;
        s2[k] = pack2(s, s); t2[k] = pack2(t, t); a2[k] = pack2(aa, aa);
        acc[k] = 0ull;
    }

#pragma unroll 8
    for (int c = 0; c < 64; c++) {
        unsigned long long wl = s_wl[c], wr = s_wr[c], we = s_we[c], bb = s_b[c];
        unsigned long long mm = s_m[c];
        unsigned mlo = (unsigned)mm, mhi = (unsigned)(mm >> 32);
#pragma unroll
        for (int k = 0; k < EPT; k++) {
            unsigned long long z = fma2(a2[k], we, bb);
            z = fma2(t2[k], wr, z);
            z = fma2(s2[k], wl, z);
            acc[k] = add2(acc[k], absor2(z, mlo, mhi));
        }
    }

    unsigned long long P = g_lin[0], Q = g_lin[1], R = g_lin[2], B = g_lin[3];
#pragma unroll
    for (int k = 0; k < EPT; k++) {
        if (!ok[k]) continue;
        unsigned long long f2 = add2(acc[k], B);
        f2 = fma2(a2[k], R, f2);
        f2 = fma2(t2[k], Q, f2);
        f2 = fma2(s2[k], P, f2);
        float f0, f1; unpack2(f2, f0, f1);
        float e0 = ex2f(f0), e1 = ex2f(f1);
        atomicAdd(&g_degattr[dsti[k]], make_float2(1.0f, av[k]));
        atomicAdd(&g_accum[dsti[k]], make_float4(e0, e0 * sv[k], e1, e1 * sv[k]));
    }
}

// ---------------------------------------------------------------------------
// self-loop contribution + finalize S = num/den
__global__ void __launch_bounds__(256) k_nodes(const float* __restrict__ x, int n)
{
    __shared__ unsigned long long s_wl[64], s_wr[64], s_we[64], s_b[64], s_m[64];
    int tid = threadIdx.x;
    if (tid < 64) {
        s_wl[tid] = g_wlA[tid]; s_wr[tid] = g_wrA[tid]; s_we[tid] = g_weA[tid];
        s_b[tid]  = g_bA[tid];  s_m[tid]  = g_sm[tid];
    }
    __syncthreads();

    int i = blockIdx.x * blockDim.x + tid;
    if (i >= n) return;

    float s = x[i];
    float2 da = g_degattr[i];
    float am = da.y / fmaxf(da.x, 1.0f);  // mean-fill self-loop attr

    unsigned long long s2 = pack2(s, s), a2 = pack2(am, am), acc = 0ull;
#pragma unroll 8
    for (int c = 0; c < 64; c++) {
        unsigned long long mm = s_m[c];
        unsigned long long z = fma2(a2, s_we[c], s_b[c]);
        z = fma2(s2, s_wr[c], z);
        z = fma2(s2, s_wl[c], z);
        acc = add2(acc, absor2(z, (unsigned)mm, (unsigned)(mm >> 32)));
    }
    unsigned long long f2 = add2(acc, g_lin[3]);
    f2 = fma2(a2, g_lin[2], f2);
    f2 = fma2(s2, g_lin[1], f2);
    f2 = fma2(s2, g_lin[0], f2);
    float f0, f1; unpack2(f2, f0, f1);
    float e0 = ex2f(f0), e1 = ex2f(f1);

    float4 ac = g_accum[i];
    float den0 = ac.x + e0, num0 = ac.y + e0 * s;
    float den1 = ac.z + e1, num1 = ac.w + e1 * s;
    g_S[i] = make_float2(num0 / den0, num1 / den1);
}

// ---------------------------------------------------------------------------
// A0, A1, C vectors (needs S[target])
__global__ void k_vec(const float* __restrict__ Wl, const float* __restrict__ bl,
                      const float* __restrict__ bout, const float* __restrict__ Wfc,
                      const float* __restrict__ bfc, const int* __restrict__ tgtp)
{
    int j = threadIdx.x;  // 0..127
    if (j >= 128) return;
    int tgt = tgtp[0];    // low 32 bits valid for int32 or int64 (little-endian)
    float2 st = g_S[tgt];
    const float* wrow = Wfc + j * 256;

    float a0 = 0.f, a1 = 0.f;
    for (int c = 0; c < 64; c++) {
        a0 += Wl[c] * wrow[c];
        a1 += Wl[64 + c] * wrow[64 + c];
    }
    float cc = bfc[j];
    for (int k = 0; k < 128; k++) {
        float cst = bl[k] + bout[k];
        cc += cst * wrow[k];
        float sh = (k < 64) ? st.x : st.y;
        float tg = Wl[k] * sh + cst;
        cc += tg * wrow[128 + k];
    }
    g_A0[j] = a0; g_A1[j] = a1; g_C[j] = cc;
}

// ---------------------------------------------------------------------------
// out[i, 0:128] = S0*A0 + S1*A1 + C  — one warp per node, float4 stores
__global__ void __launch_bounds__(256) k_out(float* __restrict__ out, int n)
{
    int lane = threadIdx.x & 31;
    int warp = (blockIdx.x * blockDim.x + threadIdx.x) >> 5;
    int nwarps = (gridDim.x * blockDim.x) >> 5;
    float4 A0v = ((const float4*)g_A0)[lane];
    float4 A1v = ((const float4*)g_A1)[lane];
    float4 Cv  = ((const float4*)g_C)[lane];
    float4* o4 = (float4*)out;
    for (int i = warp; i < n; i += nwarps) {
        float2 s = g_S[i];
        float4 o;
        o.x = fmaf(s.x, A0v.x, fmaf(s.y, A1v.x, Cv.x));
        o.y = fmaf(s.x, A0v.y, fmaf(s.y, A1v.y, Cv.y));
        o.z = fmaf(s.x, A0v.z, fmaf(s.y, A1v.z, Cv.z));
        o.w = fmaf(s.x, A0v.w, fmaf(s.y, A1v.w, Cv.w));
        o4[i * 32 + lane] = o;
    }
}

// ---------------------------------------------------------------------------
extern "C" void kernel_launch(void* const* d_in, const int* in_sizes, int n_in,
                              void* d_out, int out_size)
{
    const float* x     = (const float*)d_in[0];
    const void*  eidx  = d_in[1];
    const float* eattr = (const float*)d_in[2];
    const int*   tgtp  = (const int*)d_in[3];
    const float* Wl    = (const float*)d_in[4];
    const float* bl    = (const float*)d_in[5];
    const float* Wr    = (const float*)d_in[6];
    const float* br    = (const float*)d_in[7];
    const float* We    = (const float*)d_in[8];
    const float* att   = (const float*)d_in[9];
    const float* bout  = (const float*)d_in[10];
    const float* Wfc   = (const float*)d_in[11];
    const float* bfc   = (const float*)d_in[12];

    int n = in_sizes[0];   // N nodes (x is [N,1])
    int E = in_sizes[2];   // edges (edge_attr is [E,1])
    float* out = (float*)d_out;

    k_init<<<1, 128>>>(eidx, n, Wl, bl, Wr, br, We, att);
    k_zero<<<(n + 255) / 256, 256>>>(n);
    int ethreads = (E + EPT - 1) / EPT;
    k_edges<<<(ethreads + 255) / 256, 256>>>(x, eidx, eattr, n, E);
    k_nodes<<<(n + 255) / 256, 256>>>(x, n);
    k_vec<<<1, 128>>>(Wl, bl, bout, Wfc, bfc, tgtp);
    k_out<<<1184, 256>>>(out, n);
}